// round 4
// baseline (speedup 1.0000x reference)
#include <cuda_runtime.h>
#include <math.h>

#define N_ROWS 131072   // 32*64*64
#define DIM    64
#define KCB    512

// Output layout (concatenated, float32). Scalar perplexity misaligns
// everything after it to 4B -> scalar stores only into outE/outD.
#define OFF_Q 0
#define OFF_P (N_ROWS * DIM)
#define OFF_E (OFF_P + 1)
#define OFF_I (OFF_E + (size_t)N_ROWS * KCB)
#define OFF_D (OFF_I + N_ROWS)

#define CAND_CAP 16
#define CAND_MARGIN 6e-5f

// Scratch
__device__ float g_rownorm[N_ROWS];
__device__ float g_colnorm[KCB];
__device__ unsigned int g_count[KCB];
__device__ int g_candn[N_ROWS];
__device__ unsigned short g_cand[N_ROWS][CAND_CAP];

// ---------------------------------------------------------------------------
__device__ __forceinline__ unsigned int forder(float f) {
    unsigned int u = __float_as_uint(f);
    unsigned int mask = ((int)u >> 31) | 0x80000000u;
    return u ^ mask;  // monotonic float -> uint
}

__device__ __forceinline__ void split_tf32(float v, unsigned& hi, unsigned& lo) {
    asm("cvt.rna.tf32.f32 %0, %1;" : "=r"(hi) : "f"(v));
    float rem = v - __uint_as_float(hi);
    asm("cvt.rna.tf32.f32 %0, %1;" : "=r"(lo) : "f"(rem));
}

__device__ __forceinline__ void mma8(float* c, const unsigned* a, const unsigned* b) {
    asm volatile(
        "mma.sync.aligned.m16n8k8.row.col.f32.tf32.tf32.f32 "
        "{%0,%1,%2,%3}, {%4,%5,%6,%7}, {%8,%9}, {%0,%1,%2,%3};"
        : "+f"(c[0]), "+f"(c[1]), "+f"(c[2]), "+f"(c[3])
        : "r"(a[0]), "r"(a[1]), "r"(a[2]), "r"(a[3]), "r"(b[0]), "r"(b[1]));
}

// ---------------------------------------------------------------------------
__global__ void init_k() {
    int i = blockIdx.x * blockDim.x + threadIdx.x;
    if (i < N_ROWS) g_candn[i] = 0;
    if (i < KCB) g_count[i] = 0u;
}

__global__ void rownorm_k(const float* __restrict__ X) {
    int r = blockIdx.x * blockDim.x + threadIdx.x;
    if (r >= N_ROWS) return;
    const float4* p = (const float4*)(X + (size_t)r * DIM);
    float s = 0.f;
#pragma unroll
    for (int i = 0; i < DIM / 4; i++) {
        float4 v = p[i];
        s += v.x * v.x + v.y * v.y + v.z * v.z + v.w * v.w;
    }
    g_rownorm[r] = s;
}

__global__ void colnorm_k(const float* __restrict__ CB) {
    int r = blockIdx.x * blockDim.x + threadIdx.x;
    if (r >= KCB) return;
    const float4* p = (const float4*)(CB + (size_t)r * DIM);
    float s = 0.f;
#pragma unroll
    for (int i = 0; i < DIM / 4; i++) {
        float4 v = p[i];
        s += v.x * v.x + v.y * v.y + v.z * v.z + v.w * v.w;
    }
    g_colnorm[r] = s;
}

// ---------------------------------------------------------------------------
// tensor-core distance GEMM (3xTF32) + candidate collection.
// CTA 128 rows x 128 cols, K=64 resident. 8 warps, warp tile 32x64.
// Distances written (approx, well within 1e-3); argmin candidates
// (within CAND_MARGIN of block min) appended for the exact rescue pass.
// ---------------------------------------------------------------------------
#define AS_STRIDE 68
#define CS_STRIDE 132
#define GEMM_SMEM_BYTES (2 * 128 * AS_STRIDE * 4)

__global__ __launch_bounds__(256) void gemm_k(const float* __restrict__ A,
                                              const float* __restrict__ B,
                                              float* __restrict__ outD) {
    extern __shared__ float sm[];
    float* As = sm;                      // [128][68]
    float* Bs = sm + 128 * AS_STRIDE;    // [128][68] (scaled by 2)
    float* Cs = sm;                      // [128][132] aliases post-MMA

    const int tid = threadIdx.x;
    const int lane = tid & 31;
    const int wid = tid >> 5;
    const int g = lane >> 2;
    const int t = lane & 3;
    const int wm0 = (wid & 3) * 32;
    const int wn0 = (wid >> 2) * 64;
    const int bm0 = blockIdx.y * 128;
    const int bk0 = blockIdx.x * 128;

    {
        const float4* Ag = (const float4*)(A + (size_t)bm0 * DIM);
        const float4* Bg = (const float4*)(B + (size_t)bk0 * DIM);
#pragma unroll
        for (int i = 0; i < 8; i++) {
            int t4 = tid + i * 256;
            int row = t4 >> 4;
            int c4 = (t4 & 15) * 4;
            float4 va = Ag[t4];
            *(float4*)&As[row * AS_STRIDE + c4] = va;
            float4 vb = Bg[t4];
            vb.x *= 2.f; vb.y *= 2.f; vb.z *= 2.f; vb.w *= 2.f;
            *(float4*)&Bs[row * AS_STRIDE + c4] = vb;
        }
    }
    __syncthreads();

    float acc[2][8][4];
#pragma unroll
    for (int mi = 0; mi < 2; mi++)
#pragma unroll
        for (int ni = 0; ni < 8; ni++)
#pragma unroll
            for (int j = 0; j < 4; j++) acc[mi][ni][j] = 0.f;

#pragma unroll
    for (int k0 = 0; k0 < 64; k0 += 8) {
        unsigned ahi[2][4], alo[2][4];
#pragma unroll
        for (int mi = 0; mi < 2; mi++) {
            int r0 = wm0 + mi * 16 + g;
            split_tf32(As[r0 * AS_STRIDE + k0 + t],            ahi[mi][0], alo[mi][0]);
            split_tf32(As[(r0 + 8) * AS_STRIDE + k0 + t],      ahi[mi][1], alo[mi][1]);
            split_tf32(As[r0 * AS_STRIDE + k0 + t + 4],        ahi[mi][2], alo[mi][2]);
            split_tf32(As[(r0 + 8) * AS_STRIDE + k0 + t + 4],  ahi[mi][3], alo[mi][3]);
        }
#pragma unroll
        for (int nh = 0; nh < 2; nh++) {
            unsigned bhi[4][2], blo[4][2];
#pragma unroll
            for (int ni = 0; ni < 4; ni++) {
                int n = wn0 + (nh * 4 + ni) * 8 + g;
                split_tf32(Bs[n * AS_STRIDE + k0 + t],     bhi[ni][0], blo[ni][0]);
                split_tf32(Bs[n * AS_STRIDE + k0 + t + 4], bhi[ni][1], blo[ni][1]);
            }
#pragma unroll
            for (int mi = 0; mi < 2; mi++)
#pragma unroll
                for (int ni = 0; ni < 4; ni++) {
                    float* c = acc[mi][nh * 4 + ni];
                    mma8(c, ahi[mi], bhi[ni]);
                    mma8(c, ahi[mi], blo[ni]);
                    mma8(c, alo[mi], bhi[ni]);
                }
        }
    }

    __syncthreads();
#pragma unroll
    for (int mi = 0; mi < 2; mi++)
#pragma unroll
        for (int ni = 0; ni < 8; ni++) {
            int r0 = wm0 + mi * 16 + g;
            int c0 = wn0 + ni * 8 + 2 * t;
            Cs[r0 * CS_STRIDE + c0]           = acc[mi][ni][0];
            Cs[r0 * CS_STRIDE + c0 + 1]       = acc[mi][ni][1];
            Cs[(r0 + 8) * CS_STRIDE + c0]     = acc[mi][ni][2];
            Cs[(r0 + 8) * CS_STRIDE + c0 + 1] = acc[mi][ni][3];
        }
    __syncthreads();

    // Coalesced distance stores + candidate collection. Warp owns 16 rows.
    float cn4[4];
#pragma unroll
    for (int j = 0; j < 4; j++) cn4[j] = g_colnorm[bk0 + lane + 32 * j];

#pragma unroll 2
    for (int r = 0; r < 16; r++) {
        int lr = wid * 16 + r;
        int gr = bm0 + lr;
        float rn = g_rownorm[gr];
        const float* crow = &Cs[lr * CS_STRIDE];
        float* drow = outD + (size_t)gr * KCB + bk0;
        float v[4];
        float mn = 3.4e38f;
#pragma unroll
        for (int j = 0; j < 4; j++) {
            int c = lane + 32 * j;
            float d = (rn - crow[c]) + cn4[j];
            v[j] = d;
            drow[c] = d;
            if (d < mn) mn = d;
        }
#pragma unroll
        for (int off = 16; off > 0; off >>= 1) {
            float o = __shfl_xor_sync(0xFFFFFFFFu, mn, off);
            if (o < mn) mn = o;
        }
        float thr = mn + CAND_MARGIN;
#pragma unroll
        for (int j = 0; j < 4; j++) {
            if (v[j] <= thr) {
                int slot = atomicAdd(&g_candn[gr], 1);
                if (slot < CAND_CAP)
                    g_cand[gr][slot] = (unsigned short)(bk0 + lane + 32 * j);
            }
        }
    }
}

// ---------------------------------------------------------------------------
// finalize: exact argmin rescue over candidates (double dot, reference fp32
// rounding chain), then quantized / encodings / indices / histogram.
// One warp per row.
// ---------------------------------------------------------------------------
__global__ void finalize_k(const float* __restrict__ X, const float* __restrict__ CB,
                           float* __restrict__ outQ, float* __restrict__ outE,
                           float* __restrict__ outI) {
    int warp = blockIdx.x * (blockDim.x >> 5) + (threadIdx.x >> 5);
    int lane = threadIdx.x & 31;
    if (warp >= N_ROWS) return;

    float rn = g_rownorm[warp];
    const float4* xp4 = (const float4*)(X + (size_t)warp * DIM);
    int n = g_candn[warp];

    unsigned long long best = 0xFFFFFFFFFFFFFFFFULL;
    if (n <= CAND_CAP) {
        if (lane < n) {
            int c = g_cand[warp][lane];
            const float4* cp4 = (const float4*)(CB + (size_t)c * DIM);
            double dot = 0.0;
#pragma unroll
            for (int i = 0; i < DIM / 4; i++) {
                float4 x = xp4[i];
                float4 e = cp4[i];
                dot += (double)x.x * e.x + (double)x.y * e.y +
                       (double)x.z * e.z + (double)x.w * e.w;
            }
            float dotf = (float)dot;
            float d = (rn - 2.f * dotf) + g_colnorm[c];
            best = ((unsigned long long)forder(d) << 32) | (unsigned)c;
        }
    } else {
        // overflow fallback: exact scan of all 512 codes
        for (int it = 0; it < KCB / 32; it++) {
            int c = it * 32 + lane;
            const float4* cp4 = (const float4*)(CB + (size_t)c * DIM);
            double dot = 0.0;
#pragma unroll
            for (int i = 0; i < DIM / 4; i++) {
                float4 x = xp4[i];
                float4 e = cp4[i];
                dot += (double)x.x * e.x + (double)x.y * e.y +
                       (double)x.z * e.z + (double)x.w * e.w;
            }
            float dotf = (float)dot;
            float d = (rn - 2.f * dotf) + g_colnorm[c];
            unsigned long long key =
                ((unsigned long long)forder(d) << 32) | (unsigned)c;
            if (key < best) best = key;
        }
    }
#pragma unroll
    for (int off = 16; off > 0; off >>= 1) {
        unsigned long long o = __shfl_xor_sync(0xFFFFFFFFu, best, off);
        if (o < best) best = o;
    }
    int idx = (int)(best & 0xFFFFFFFFu);

    // quantized (outQ 16B-aligned): x + (cb - x)
    const float2* xp = (const float2*)(X + (size_t)warp * DIM);
    const float2* cp = (const float2*)(CB + (size_t)idx * DIM);
    float2 x = xp[lane];
    float2 c2 = cp[lane];
    float2 q;
    q.x = x.x + (c2.x - x.x);
    q.y = x.y + (c2.y - x.y);
    ((float2*)(outQ + (size_t)warp * DIM))[lane] = q;

    if (lane == 0) {
        outI[warp] = (float)idx;
        atomicAdd(&g_count[idx], 1u);
    }

    // one-hot encodings: scalar coalesced (outE only 4B-aligned)
    float* ep = outE + (size_t)warp * KCB;
#pragma unroll
    for (int j = 0; j < 16; j++) {
        int col = j * 32 + lane;
        ep[col] = (col == idx) ? 1.f : 0.f;
    }
}

// ---------------------------------------------------------------------------
__global__ void perp_k(float* __restrict__ outP) {
    __shared__ float s[KCB];
    int t = threadIdx.x;
    float p = (float)g_count[t] / (float)N_ROWS;
    s[t] = p * logf(p + 1e-10f);
    __syncthreads();
    for (int o = KCB / 2; o > 0; o >>= 1) {
        if (t < o) s[t] += s[t + o];
        __syncthreads();
    }
    if (t == 0) outP[0] = expf(-s[0]);
}

// ---------------------------------------------------------------------------
extern "C" void kernel_launch(void* const* d_in, const int* in_sizes, int n_in,
                              void* d_out, int out_size) {
    const float* X = (const float*)d_in[0];
    const float* CB = (const float*)d_in[1];
    if (n_in >= 2 && in_sizes[0] == KCB * DIM) {
        X = (const float*)d_in[1];
        CB = (const float*)d_in[0];
    }
    float* out = (float*)d_out;
    float* outQ = out + OFF_Q;
    float* outP = out + OFF_P;
    float* outE = out + OFF_E;
    float* outI = out + OFF_I;
    float* outD = out + OFF_D;

    cudaFuncSetAttribute(gemm_k, cudaFuncAttributeMaxDynamicSharedMemorySize,
                         GEMM_SMEM_BYTES);

    init_k<<<N_ROWS / 256, 256>>>();
    rownorm_k<<<N_ROWS / 256, 256>>>(X);
    colnorm_k<<<2, 256>>>(CB);
    gemm_k<<<dim3(KCB / 128, N_ROWS / 128), 256, GEMM_SMEM_BYTES>>>(X, CB, outD);
    finalize_k<<<N_ROWS / 8, 256>>>(X, CB, outQ, outE, outI);
    perp_k<<<1, KCB>>>(outP);
}

// round 5
// speedup vs baseline: 1.4807x; 1.4807x over previous
#include <cuda_runtime.h>
#include <math.h>

#define N_ROWS 131072   // 32*64*64
#define DIM    64
#define KCB    512

// Output layout (concatenated, float32). Scalar perplexity misaligns
// everything after it to 4B -> scalar stores only into outE/outD.
#define OFF_Q 0
#define OFF_P (N_ROWS * DIM)
#define OFF_E (OFF_P + 1)
#define OFF_I (OFF_E + (size_t)N_ROWS * KCB)
#define OFF_D (OFF_I + N_ROWS)

#define CAND_CAP 16
#define CAND_MARGIN 1e-4f

// Scratch
__device__ float g_rownorm[N_ROWS];
__device__ float g_colnorm[KCB];
__device__ unsigned int g_count[KCB];
__device__ int g_candn[N_ROWS];
__device__ unsigned short g_cand[N_ROWS][CAND_CAP];

// ---------------------------------------------------------------------------
__device__ __forceinline__ unsigned int forder(float f) {
    unsigned int u = __float_as_uint(f);
    unsigned int mask = ((int)u >> 31) | 0x80000000u;
    return u ^ mask;  // monotonic float -> uint
}

__device__ __forceinline__ float cvt_tf32(float v) {
    unsigned r;
    asm("cvt.rna.tf32.f32 %0, %1;" : "=r"(r) : "f"(v));
    return __uint_as_float(r);
}

__device__ __forceinline__ void mma8(float* c, const float* a, const float* b) {
    asm volatile(
        "mma.sync.aligned.m16n8k8.row.col.f32.tf32.tf32.f32 "
        "{%0,%1,%2,%3}, {%4,%5,%6,%7}, {%8,%9}, {%0,%1,%2,%3};"
        : "+f"(c[0]), "+f"(c[1]), "+f"(c[2]), "+f"(c[3])
        : "r"(__float_as_uint(a[0])), "r"(__float_as_uint(a[1])),
          "r"(__float_as_uint(a[2])), "r"(__float_as_uint(a[3])),
          "r"(__float_as_uint(b[0])), "r"(__float_as_uint(b[1])));
}

// ---------------------------------------------------------------------------
// row norms ||x||^2 (+ candidate-count reset folded in)
__global__ void rownorm_k(const float* __restrict__ X) {
    int r = blockIdx.x * blockDim.x + threadIdx.x;
    if (r >= N_ROWS) return;
    g_candn[r] = 0;
    const float4* p = (const float4*)(X + (size_t)r * DIM);
    float s = 0.f;
#pragma unroll
    for (int i = 0; i < DIM / 4; i++) {
        float4 v = p[i];
        s += v.x * v.x + v.y * v.y + v.z * v.z + v.w * v.w;
    }
    g_rownorm[r] = s;
}

// codebook norms ||e||^2 (+ count reset folded in)
__global__ void colnorm_k(const float* __restrict__ CB) {
    int r = blockIdx.x * blockDim.x + threadIdx.x;
    if (r >= KCB) return;
    g_count[r] = 0u;
    const float4* p = (const float4*)(CB + (size_t)r * DIM);
    float s = 0.f;
#pragma unroll
    for (int i = 0; i < DIM / 4; i++) {
        float4 v = p[i];
        s += v.x * v.x + v.y * v.y + v.z * v.z + v.w * v.w;
    }
    g_colnorm[r] = s;
}

// ---------------------------------------------------------------------------
// tensor-core distance GEMM + candidate collection.
// 2-MMA split scheme: A pre-split hi/lo in smem (once), B single tf32 cvt.
// dot ~= (a_hi + a_lo) * b_hi ; dropped a*b_lo ~1e-5 worst-case, covered by
// CAND_MARGIN in the rescue pass. CTA 128x128, K=64 resident, 8 warps 32x64.
// ---------------------------------------------------------------------------
#define AS_STRIDE 68
#define CS_STRIDE 132
#define SM_AHI 0
#define SM_ALO (128 * AS_STRIDE)
#define SM_BHI (2 * 128 * AS_STRIDE)
#define GEMM_SMEM_BYTES (3 * 128 * AS_STRIDE * 4)

__global__ __launch_bounds__(256) void gemm_k(const float* __restrict__ A,
                                              const float* __restrict__ B,
                                              float* __restrict__ outD) {
    extern __shared__ float sm[];
    float* Ahi = sm + SM_AHI;   // [128][68] tf32 bits in f32 container
    float* Alo = sm + SM_ALO;   // [128][68]
    float* Bhi = sm + SM_BHI;   // [128][68] (2*codebook, tf32)
    float* Cs = sm;             // [128][132] aliases Ahi/Alo post-MMA

    const int tid = threadIdx.x;
    const int lane = tid & 31;
    const int wid = tid >> 5;
    const int g = lane >> 2;
    const int t = lane & 3;
    const int wm0 = (wid & 3) * 32;
    const int wn0 = (wid >> 2) * 64;
    const int bm0 = blockIdx.y * 128;
    const int bk0 = blockIdx.x * 128;

    // Tile load + one-time tf32 split (A) / cvt (B)
    {
        const float4* Ag = (const float4*)(A + (size_t)bm0 * DIM);
        const float4* Bg = (const float4*)(B + (size_t)bk0 * DIM);
#pragma unroll
        for (int i = 0; i < 8; i++) {
            int t4 = tid + i * 256;        // 0..2047
            int row = t4 >> 4;
            int c4 = (t4 & 15) * 4;
            float4 va = Ag[t4];
            float4 vh, vl;
            vh.x = cvt_tf32(va.x); vl.x = cvt_tf32(va.x - vh.x);
            vh.y = cvt_tf32(va.y); vl.y = cvt_tf32(va.y - vh.y);
            vh.z = cvt_tf32(va.z); vl.z = cvt_tf32(va.z - vh.z);
            vh.w = cvt_tf32(va.w); vl.w = cvt_tf32(va.w - vh.w);
            *(float4*)&Ahi[row * AS_STRIDE + c4] = vh;
            *(float4*)&Alo[row * AS_STRIDE + c4] = vl;
            float4 vb = Bg[t4];
            float4 bh;
            bh.x = cvt_tf32(2.f * vb.x);
            bh.y = cvt_tf32(2.f * vb.y);
            bh.z = cvt_tf32(2.f * vb.z);
            bh.w = cvt_tf32(2.f * vb.w);
            *(float4*)&Bhi[row * AS_STRIDE + c4] = bh;
        }
    }
    __syncthreads();

    float acc[2][8][4];
#pragma unroll
    for (int mi = 0; mi < 2; mi++)
#pragma unroll
        for (int ni = 0; ni < 8; ni++)
#pragma unroll
            for (int j = 0; j < 4; j++) acc[mi][ni][j] = 0.f;

#pragma unroll
    for (int k0 = 0; k0 < 64; k0 += 8) {
        float ah[2][4], al[2][4];
#pragma unroll
        for (int mi = 0; mi < 2; mi++) {
            int r0 = wm0 + mi * 16 + g;
            ah[mi][0] = Ahi[r0 * AS_STRIDE + k0 + t];
            ah[mi][1] = Ahi[(r0 + 8) * AS_STRIDE + k0 + t];
            ah[mi][2] = Ahi[r0 * AS_STRIDE + k0 + t + 4];
            ah[mi][3] = Ahi[(r0 + 8) * AS_STRIDE + k0 + t + 4];
            al[mi][0] = Alo[r0 * AS_STRIDE + k0 + t];
            al[mi][1] = Alo[(r0 + 8) * AS_STRIDE + k0 + t];
            al[mi][2] = Alo[r0 * AS_STRIDE + k0 + t + 4];
            al[mi][3] = Alo[(r0 + 8) * AS_STRIDE + k0 + t + 4];
        }
#pragma unroll
        for (int nh = 0; nh < 2; nh++) {
            float bh[4][2];
#pragma unroll
            for (int ni = 0; ni < 4; ni++) {
                int n = wn0 + (nh * 4 + ni) * 8 + g;
                bh[ni][0] = Bhi[n * AS_STRIDE + k0 + t];
                bh[ni][1] = Bhi[n * AS_STRIDE + k0 + t + 4];
            }
#pragma unroll
            for (int mi = 0; mi < 2; mi++)
#pragma unroll
                for (int ni = 0; ni < 4; ni++) {
                    float* c = acc[mi][nh * 4 + ni];
                    mma8(c, ah[mi], bh[ni]);
                    mma8(c, al[mi], bh[ni]);
                }
        }
    }

    __syncthreads();
#pragma unroll
    for (int mi = 0; mi < 2; mi++)
#pragma unroll
        for (int ni = 0; ni < 8; ni++) {
            int r0 = wm0 + mi * 16 + g;
            int c0 = wn0 + ni * 8 + 2 * t;
            Cs[r0 * CS_STRIDE + c0]           = acc[mi][ni][0];
            Cs[r0 * CS_STRIDE + c0 + 1]       = acc[mi][ni][1];
            Cs[(r0 + 8) * CS_STRIDE + c0]     = acc[mi][ni][2];
            Cs[(r0 + 8) * CS_STRIDE + c0 + 1] = acc[mi][ni][3];
        }
    __syncthreads();

    // Coalesced distance stores + candidate collection. Warp owns 16 rows.
    float cn4[4];
#pragma unroll
    for (int j = 0; j < 4; j++) cn4[j] = g_colnorm[bk0 + lane + 32 * j];

#pragma unroll 2
    for (int r = 0; r < 16; r++) {
        int lr = wid * 16 + r;
        int gr = bm0 + lr;
        float rn = g_rownorm[gr];
        const float* crow = &Cs[lr * CS_STRIDE];
        float* drow = outD + (size_t)gr * KCB + bk0;
        float v[4];
        float mn = 3.4e38f;
#pragma unroll
        for (int j = 0; j < 4; j++) {
            int c = lane + 32 * j;
            float d = (rn - crow[c]) + cn4[j];
            v[j] = d;
            drow[c] = d;
            if (d < mn) mn = d;
        }
#pragma unroll
        for (int off = 16; off > 0; off >>= 1) {
            float o = __shfl_xor_sync(0xFFFFFFFFu, mn, off);
            if (o < mn) mn = o;
        }
        float thr = mn + CAND_MARGIN;
#pragma unroll
        for (int j = 0; j < 4; j++) {
            if (v[j] <= thr) {
                int slot = atomicAdd(&g_candn[gr], 1);
                if (slot < CAND_CAP)
                    g_cand[gr][slot] = (unsigned short)(bk0 + lane + 32 * j);
            }
        }
    }
}

// ---------------------------------------------------------------------------
// finalize: exact-argmin rescue over candidates with PLAIN FP32 dot (matches
// reference's own fp32 accumulation error scale ~1e-9), then quantized /
// encodings / indices / histogram. One warp per row.
// ---------------------------------------------------------------------------
__global__ void finalize_k(const float* __restrict__ X, const float* __restrict__ CB,
                           float* __restrict__ outQ, float* __restrict__ outE,
                           float* __restrict__ outI) {
    int warp = blockIdx.x * (blockDim.x >> 5) + (threadIdx.x >> 5);
    int lane = threadIdx.x & 31;
    if (warp >= N_ROWS) return;

    float rn = g_rownorm[warp];
    const float4* xp4 = (const float4*)(X + (size_t)warp * DIM);
    int n = g_candn[warp];

    unsigned long long best = 0xFFFFFFFFFFFFFFFFULL;
    if (n <= CAND_CAP) {
        if (lane < n) {
            int c = g_cand[warp][lane];
            const float4* cp4 = (const float4*)(CB + (size_t)c * DIM);
            float dot = 0.f;
#pragma unroll
            for (int i = 0; i < DIM / 4; i++) {
                float4 x = xp4[i];
                float4 e = cp4[i];
                dot = fmaf(x.x, e.x, dot);
                dot = fmaf(x.y, e.y, dot);
                dot = fmaf(x.z, e.z, dot);
                dot = fmaf(x.w, e.w, dot);
            }
            float d = (rn - 2.f * dot) + g_colnorm[c];
            best = ((unsigned long long)forder(d) << 32) | (unsigned)c;
        }
    } else {
        // overflow fallback: exact fp32 scan of all 512 codes
        for (int it = 0; it < KCB / 32; it++) {
            int c = it * 32 + lane;
            const float4* cp4 = (const float4*)(CB + (size_t)c * DIM);
            float dot = 0.f;
#pragma unroll
            for (int i = 0; i < DIM / 4; i++) {
                float4 x = xp4[i];
                float4 e = cp4[i];
                dot = fmaf(x.x, e.x, dot);
                dot = fmaf(x.y, e.y, dot);
                dot = fmaf(x.z, e.z, dot);
                dot = fmaf(x.w, e.w, dot);
            }
            float d = (rn - 2.f * dot) + g_colnorm[c];
            unsigned long long key =
                ((unsigned long long)forder(d) << 32) | (unsigned)c;
            if (key < best) best = key;
        }
    }
#pragma unroll
    for (int off = 16; off > 0; off >>= 1) {
        unsigned long long o = __shfl_xor_sync(0xFFFFFFFFu, best, off);
        if (o < best) best = o;
    }
    int idx = (int)(best & 0xFFFFFFFFu);

    // quantized (outQ 16B-aligned): x + (cb - x)
    const float2* xp = (const float2*)(X + (size_t)warp * DIM);
    const float2* cp = (const float2*)(CB + (size_t)idx * DIM);
    float2 x = xp[lane];
    float2 c2 = cp[lane];
    float2 q;
    q.x = x.x + (c2.x - x.x);
    q.y = x.y + (c2.y - x.y);
    ((float2*)(outQ + (size_t)warp * DIM))[lane] = q;

    if (lane == 0) {
        outI[warp] = (float)idx;
        atomicAdd(&g_count[idx], 1u);
    }

    // one-hot encodings: scalar coalesced (outE only 4B-aligned)
    float* ep = outE + (size_t)warp * KCB;
#pragma unroll
    for (int j = 0; j < 16; j++) {
        int col = j * 32 + lane;
        ep[col] = (col == idx) ? 1.f : 0.f;
    }
}

// ---------------------------------------------------------------------------
__global__ void perp_k(float* __restrict__ outP) {
    __shared__ float s[KCB];
    int t = threadIdx.x;
    float p = (float)g_count[t] / (float)N_ROWS;
    s[t] = p * logf(p + 1e-10f);
    __syncthreads();
    for (int o = KCB / 2; o > 0; o >>= 1) {
        if (t < o) s[t] += s[t + o];
        __syncthreads();
    }
    if (t == 0) outP[0] = expf(-s[0]);
}

// ---------------------------------------------------------------------------
extern "C" void kernel_launch(void* const* d_in, const int* in_sizes, int n_in,
                              void* d_out, int out_size) {
    const float* X = (const float*)d_in[0];
    const float* CB = (const float*)d_in[1];
    if (n_in >= 2 && in_sizes[0] == KCB * DIM) {
        X = (const float*)d_in[1];
        CB = (const float*)d_in[0];
    }
    float* out = (float*)d_out;
    float* outQ = out + OFF_Q;
    float* outP = out + OFF_P;
    float* outE = out + OFF_E;
    float* outI = out + OFF_I;
    float* outD = out + OFF_D;

    cudaFuncSetAttribute(gemm_k, cudaFuncAttributeMaxDynamicSharedMemorySize,
                         GEMM_SMEM_BYTES);

    rownorm_k<<<N_ROWS / 256, 256>>>(X);
    colnorm_k<<<2, 256>>>(CB);
    gemm_k<<<dim3(KCB / 128, N_ROWS / 128), 256, GEMM_SMEM_BYTES>>>(X, CB, outD);
    finalize_k<<<N_ROWS / 8, 256>>>(X, CB, outQ, outE, outI);
    perp_k<<<1, KCB>>>(outP);
}

// round 6
// speedup vs baseline: 1.5414x; 1.0410x over previous
#include <cuda_runtime.h>
#include <math.h>

#define N_ROWS 131072   // 32*64*64
#define DIM    64
#define KCB    512

// Output layout (concatenated, float32). Scalar perplexity misaligns
// everything after it to 4B -> scalar stores only into outE/outD.
#define OFF_Q 0
#define OFF_P (N_ROWS * DIM)
#define OFF_E (OFF_P + 1)
#define OFF_I (OFF_E + (size_t)N_ROWS * KCB)
#define OFF_D (OFF_I + N_ROWS)

#define CAND_CAP 16
#define CAND_MARGIN 1e-3f

// Scratch
__device__ float g_rownorm[N_ROWS];
__device__ float g_colnorm[KCB];
__device__ unsigned int g_count[KCB];
__device__ int g_candn[N_ROWS];
__device__ int g_idx[N_ROWS];
__device__ unsigned short g_cand[N_ROWS][CAND_CAP];

// ---------------------------------------------------------------------------
__device__ __forceinline__ unsigned int forder(float f) {
    unsigned int u = __float_as_uint(f);
    unsigned int mask = ((int)u >> 31) | 0x80000000u;
    return u ^ mask;  // monotonic float -> uint
}

__device__ __forceinline__ float cvt_tf32(float v) {
    unsigned r;
    asm("cvt.rna.tf32.f32 %0, %1;" : "=r"(r) : "f"(v));
    return __uint_as_float(r);
}

__device__ __forceinline__ void mma8(float* c, const float* a, const float* b) {
    asm volatile(
        "mma.sync.aligned.m16n8k8.row.col.f32.tf32.tf32.f32 "
        "{%0,%1,%2,%3}, {%4,%5,%6,%7}, {%8,%9}, {%0,%1,%2,%3};"
        : "+f"(c[0]), "+f"(c[1]), "+f"(c[2]), "+f"(c[3])
        : "r"(__float_as_uint(a[0])), "r"(__float_as_uint(a[1])),
          "r"(__float_as_uint(a[2])), "r"(__float_as_uint(a[3])),
          "r"(__float_as_uint(b[0])), "r"(__float_as_uint(b[1])));
}

// ---------------------------------------------------------------------------
__global__ void rownorm_k(const float* __restrict__ X) {
    int r = blockIdx.x * blockDim.x + threadIdx.x;
    if (r >= N_ROWS) return;
    g_candn[r] = 0;
    const float4* p = (const float4*)(X + (size_t)r * DIM);
    float s = 0.f;
#pragma unroll
    for (int i = 0; i < DIM / 4; i++) {
        float4 v = p[i];
        s += v.x * v.x + v.y * v.y + v.z * v.z + v.w * v.w;
    }
    g_rownorm[r] = s;
}

__global__ void colnorm_k(const float* __restrict__ CB) {
    int r = blockIdx.x * blockDim.x + threadIdx.x;
    if (r >= KCB) return;
    g_count[r] = 0u;
    const float4* p = (const float4*)(CB + (size_t)r * DIM);
    float s = 0.f;
#pragma unroll
    for (int i = 0; i < DIM / 4; i++) {
        float4 v = p[i];
        s += v.x * v.x + v.y * v.y + v.z * v.z + v.w * v.w;
    }
    g_colnorm[r] = s;
}

// ---------------------------------------------------------------------------
// tensor-core distance GEMM (single tf32 MMA) + candidate collection.
// abs distance error <= ~3e-4 (covered by CAND_MARGIN in rescue; distances
// output tolerance is 1e-3 REL at |d|~64 -> plenty).
// CTA 128x128, K=64 resident, 8 warps, warp tile 32x64.
// ---------------------------------------------------------------------------
#define AS_STRIDE 68
#define CS_STRIDE 132
#define GEMM_SMEM_BYTES (2 * 128 * AS_STRIDE * 4)

__global__ __launch_bounds__(256) void gemm_k(const float* __restrict__ A,
                                              const float* __restrict__ B,
                                              float* __restrict__ outD) {
    extern __shared__ float sm[];
    float* As = sm;                      // [128][68] tf32(A)
    float* Bs = sm + 128 * AS_STRIDE;    // [128][68] tf32(2*codebook)
    float* Cs = sm;                      // [128][132] aliases post-MMA

    const int tid = threadIdx.x;
    const int lane = tid & 31;
    const int wid = tid >> 5;
    const int g = lane >> 2;
    const int t = lane & 3;
    const int wm0 = (wid & 3) * 32;
    const int wn0 = (wid >> 2) * 64;
    const int bm0 = blockIdx.y * 128;
    const int bk0 = blockIdx.x * 128;

    {
        const float4* Ag = (const float4*)(A + (size_t)bm0 * DIM);
        const float4* Bg = (const float4*)(B + (size_t)bk0 * DIM);
#pragma unroll
        for (int i = 0; i < 8; i++) {
            int t4 = tid + i * 256;        // 0..2047
            int row = t4 >> 4;
            int c4 = (t4 & 15) * 4;
            float4 va = Ag[t4];
            float4 vh;
            vh.x = cvt_tf32(va.x);
            vh.y = cvt_tf32(va.y);
            vh.z = cvt_tf32(va.z);
            vh.w = cvt_tf32(va.w);
            *(float4*)&As[row * AS_STRIDE + c4] = vh;
            float4 vb = Bg[t4];
            float4 bh;
            bh.x = cvt_tf32(2.f * vb.x);
            bh.y = cvt_tf32(2.f * vb.y);
            bh.z = cvt_tf32(2.f * vb.z);
            bh.w = cvt_tf32(2.f * vb.w);
            *(float4*)&Bs[row * AS_STRIDE + c4] = bh;
        }
    }
    __syncthreads();

    float acc[2][8][4];
#pragma unroll
    for (int mi = 0; mi < 2; mi++)
#pragma unroll
        for (int ni = 0; ni < 8; ni++)
#pragma unroll
            for (int j = 0; j < 4; j++) acc[mi][ni][j] = 0.f;

#pragma unroll
    for (int k0 = 0; k0 < 64; k0 += 8) {
        float ah[2][4];
#pragma unroll
        for (int mi = 0; mi < 2; mi++) {
            int r0 = wm0 + mi * 16 + g;
            ah[mi][0] = As[r0 * AS_STRIDE + k0 + t];
            ah[mi][1] = As[(r0 + 8) * AS_STRIDE + k0 + t];
            ah[mi][2] = As[r0 * AS_STRIDE + k0 + t + 4];
            ah[mi][3] = As[(r0 + 8) * AS_STRIDE + k0 + t + 4];
        }
#pragma unroll
        for (int nh = 0; nh < 2; nh++) {
            float bh[4][2];
#pragma unroll
            for (int ni = 0; ni < 4; ni++) {
                int n = wn0 + (nh * 4 + ni) * 8 + g;
                bh[ni][0] = Bs[n * AS_STRIDE + k0 + t];
                bh[ni][1] = Bs[n * AS_STRIDE + k0 + t + 4];
            }
#pragma unroll
            for (int mi = 0; mi < 2; mi++)
#pragma unroll
                for (int ni = 0; ni < 4; ni++)
                    mma8(acc[mi][nh * 4 + ni], ah[mi], bh[ni]);
        }
    }

    __syncthreads();
#pragma unroll
    for (int mi = 0; mi < 2; mi++)
#pragma unroll
        for (int ni = 0; ni < 8; ni++) {
            int r0 = wm0 + mi * 16 + g;
            int c0 = wn0 + ni * 8 + 2 * t;
            Cs[r0 * CS_STRIDE + c0]           = acc[mi][ni][0];
            Cs[r0 * CS_STRIDE + c0 + 1]       = acc[mi][ni][1];
            Cs[(r0 + 8) * CS_STRIDE + c0]     = acc[mi][ni][2];
            Cs[(r0 + 8) * CS_STRIDE + c0 + 1] = acc[mi][ni][3];
        }
    __syncthreads();

    // Coalesced distance stores + candidate collection. Warp owns 16 rows.
    float cn4[4];
#pragma unroll
    for (int j = 0; j < 4; j++) cn4[j] = g_colnorm[bk0 + lane + 32 * j];

#pragma unroll 2
    for (int r = 0; r < 16; r++) {
        int lr = wid * 16 + r;
        int gr = bm0 + lr;
        float rn = g_rownorm[gr];
        const float* crow = &Cs[lr * CS_STRIDE];
        float* drow = outD + (size_t)gr * KCB + bk0;
        float v[4];
        float mn = 3.4e38f;
#pragma unroll
        for (int j = 0; j < 4; j++) {
            int c = lane + 32 * j;
            float d = (rn - crow[c]) + cn4[j];
            v[j] = d;
            drow[c] = d;
            if (d < mn) mn = d;
        }
#pragma unroll
        for (int off = 16; off > 0; off >>= 1) {
            float o = __shfl_xor_sync(0xFFFFFFFFu, mn, off);
            if (o < mn) mn = o;
        }
        float thr = mn + CAND_MARGIN;
#pragma unroll
        for (int j = 0; j < 4; j++) {
            if (v[j] <= thr) {
                int slot = atomicAdd(&g_candn[gr], 1);
                if (slot < CAND_CAP)
                    g_cand[gr][slot] = (unsigned short)(bk0 + lane + 32 * j);
            }
        }
    }
}

// ---------------------------------------------------------------------------
// rescue: exact fp32 argmin over candidates (same numerics as the passing
// R5 kernel). One warp per row. Writes g_idx, indices output, histogram.
// ---------------------------------------------------------------------------
__global__ void rescue_k(const float* __restrict__ X, const float* __restrict__ CB,
                         float* __restrict__ outI) {
    int warp = blockIdx.x * (blockDim.x >> 5) + (threadIdx.x >> 5);
    int lane = threadIdx.x & 31;
    if (warp >= N_ROWS) return;

    float rn = g_rownorm[warp];
    const float4* xp4 = (const float4*)(X + (size_t)warp * DIM);
    int n = g_candn[warp];

    unsigned long long best = 0xFFFFFFFFFFFFFFFFULL;
    if (n <= CAND_CAP) {
        if (lane < n) {
            int c = g_cand[warp][lane];
            const float4* cp4 = (const float4*)(CB + (size_t)c * DIM);
            float dot = 0.f;
#pragma unroll
            for (int i = 0; i < DIM / 4; i++) {
                float4 x = xp4[i];
                float4 e = cp4[i];
                dot = fmaf(x.x, e.x, dot);
                dot = fmaf(x.y, e.y, dot);
                dot = fmaf(x.z, e.z, dot);
                dot = fmaf(x.w, e.w, dot);
            }
            float d = (rn - 2.f * dot) + g_colnorm[c];
            best = ((unsigned long long)forder(d) << 32) | (unsigned)c;
        }
    } else {
        // overflow fallback: exact fp32 scan of all 512 codes
        for (int it = 0; it < KCB / 32; it++) {
            int c = it * 32 + lane;
            const float4* cp4 = (const float4*)(CB + (size_t)c * DIM);
            float dot = 0.f;
#pragma unroll
            for (int i = 0; i < DIM / 4; i++) {
                float4 x = xp4[i];
                float4 e = cp4[i];
                dot = fmaf(x.x, e.x, dot);
                dot = fmaf(x.y, e.y, dot);
                dot = fmaf(x.z, e.z, dot);
                dot = fmaf(x.w, e.w, dot);
            }
            float d = (rn - 2.f * dot) + g_colnorm[c];
            unsigned long long key =
                ((unsigned long long)forder(d) << 32) | (unsigned)c;
            if (key < best) best = key;
        }
    }
#pragma unroll
    for (int off = 16; off > 0; off >>= 1) {
        unsigned long long o = __shfl_xor_sync(0xFFFFFFFFu, best, off);
        if (o < best) best = o;
    }
    if (lane == 0) {
        int idx = (int)(best & 0xFFFFFFFFu);
        g_idx[warp] = idx;
        outI[warp] = (float)idx;
        atomicAdd(&g_count[idx], 1u);
    }
}

// ---------------------------------------------------------------------------
// output: pure streaming writer (quantized + one-hot encodings).
// One warp per row, minimal registers -> high occupancy.
// ---------------------------------------------------------------------------
__global__ void output_k(const float* __restrict__ X, const float* __restrict__ CB,
                         float* __restrict__ outQ, float* __restrict__ outE) {
    int warp = blockIdx.x * (blockDim.x >> 5) + (threadIdx.x >> 5);
    int lane = threadIdx.x & 31;
    if (warp >= N_ROWS) return;

    int idx = g_idx[warp];

    // quantized (outQ 16B-aligned): x + (cb - x)
    const float2* xp = (const float2*)(X + (size_t)warp * DIM);
    const float2* cp = (const float2*)(CB + (size_t)idx * DIM);
    float2 x = xp[lane];
    float2 c2 = cp[lane];
    float2 q;
    q.x = x.x + (c2.x - x.x);
    q.y = x.y + (c2.y - x.y);
    ((float2*)(outQ + (size_t)warp * DIM))[lane] = q;

    // one-hot encodings: scalar coalesced (outE only 4B-aligned)
    float* ep = outE + (size_t)warp * KCB;
#pragma unroll
    for (int j = 0; j < 16; j++) {
        int col = j * 32 + lane;
        ep[col] = (col == idx) ? 1.f : 0.f;
    }
}

// ---------------------------------------------------------------------------
__global__ void perp_k(float* __restrict__ outP) {
    __shared__ float s[KCB];
    int t = threadIdx.x;
    float p = (float)g_count[t] / (float)N_ROWS;
    s[t] = p * logf(p + 1e-10f);
    __syncthreads();
    for (int o = KCB / 2; o > 0; o >>= 1) {
        if (t < o) s[t] += s[t + o];
        __syncthreads();
    }
    if (t == 0) outP[0] = expf(-s[0]);
}

// ---------------------------------------------------------------------------
extern "C" void kernel_launch(void* const* d_in, const int* in_sizes, int n_in,
                              void* d_out, int out_size) {
    const float* X = (const float*)d_in[0];
    const float* CB = (const float*)d_in[1];
    if (n_in >= 2 && in_sizes[0] == KCB * DIM) {
        X = (const float*)d_in[1];
        CB = (const float*)d_in[0];
    }
    float* out = (float*)d_out;
    float* outQ = out + OFF_Q;
    float* outP = out + OFF_P;
    float* outE = out + OFF_E;
    float* outI = out + OFF_I;
    float* outD = out + OFF_D;

    cudaFuncSetAttribute(gemm_k, cudaFuncAttributeMaxDynamicSharedMemorySize,
                         GEMM_SMEM_BYTES);

    rownorm_k<<<N_ROWS / 256, 256>>>(X);
    colnorm_k<<<2, 256>>>(CB);
    gemm_k<<<dim3(KCB / 128, N_ROWS / 128), 256, GEMM_SMEM_BYTES>>>(X, CB, outD);
    rescue_k<<<N_ROWS / 8, 256>>>(X, CB, outI);
    output_k<<<N_ROWS / 8, 256>>>(X, CB, outQ, outE);
    perp_k<<<1, KCB>>>(outP);
}

// round 7
// speedup vs baseline: 1.8483x; 1.1992x over previous
#include <cuda_runtime.h>
#include <math.h>

#define N_ROWS 131072   // 32*64*64
#define DIM    64
#define KCB    512

// Output layout (concatenated, float32). Scalar perplexity misaligns
// everything after it to 4B -> scalar stores only into outE/outD.
#define OFF_Q 0
#define OFF_P (N_ROWS * DIM)
#define OFF_E (OFF_P + 1)
#define OFF_I (OFF_E + (size_t)N_ROWS * KCB)
#define OFF_D (OFF_I + N_ROWS)

#define CAND_CAP 16
#define CAND_MARGIN 1e-3f

// Scratch
__device__ float g_rownorm[N_ROWS];
__device__ float g_colnorm[KCB];
__device__ unsigned int g_count[KCB];
__device__ int g_candn[N_ROWS];
__device__ unsigned short g_cand[N_ROWS][CAND_CAP];

// ---------------------------------------------------------------------------
__device__ __forceinline__ unsigned int forder(float f) {
    unsigned int u = __float_as_uint(f);
    unsigned int mask = ((int)u >> 31) | 0x80000000u;
    return u ^ mask;  // monotonic float -> uint
}

__device__ __forceinline__ float cvt_tf32(float v) {
    unsigned r;
    asm("cvt.rna.tf32.f32 %0, %1;" : "=r"(r) : "f"(v));
    return __uint_as_float(r);
}

__device__ __forceinline__ void mma8(float* c, const float* a, const float* b) {
    asm volatile(
        "mma.sync.aligned.m16n8k8.row.col.f32.tf32.tf32.f32 "
        "{%0,%1,%2,%3}, {%4,%5,%6,%7}, {%8,%9}, {%0,%1,%2,%3};"
        : "+f"(c[0]), "+f"(c[1]), "+f"(c[2]), "+f"(c[3])
        : "r"(__float_as_uint(a[0])), "r"(__float_as_uint(a[1])),
          "r"(__float_as_uint(a[2])), "r"(__float_as_uint(a[3])),
          "r"(__float_as_uint(b[0])), "r"(__float_as_uint(b[1])));
}

// ---------------------------------------------------------------------------
__global__ void rownorm_k(const float* __restrict__ X) {
    int r = blockIdx.x * blockDim.x + threadIdx.x;
    if (r >= N_ROWS) return;
    g_candn[r] = 0;
    const float4* p = (const float4*)(X + (size_t)r * DIM);
    float s = 0.f;
#pragma unroll
    for (int i = 0; i < DIM / 4; i++) {
        float4 v = p[i];
        s += v.x * v.x + v.y * v.y + v.z * v.z + v.w * v.w;
    }
    g_rownorm[r] = s;
}

__global__ void colnorm_k(const float* __restrict__ CB) {
    int r = blockIdx.x * blockDim.x + threadIdx.x;
    if (r >= KCB) return;
    g_count[r] = 0u;
    const float4* p = (const float4*)(CB + (size_t)r * DIM);
    float s = 0.f;
#pragma unroll
    for (int i = 0; i < DIM / 4; i++) {
        float4 v = p[i];
        s += v.x * v.x + v.y * v.y + v.z * v.z + v.w * v.w;
    }
    g_colnorm[r] = s;
}

// ---------------------------------------------------------------------------
// tensor-core distance GEMM (single tf32 MMA) + candidate collection.
// abs distance error <= ~3e-4 (covered by CAND_MARGIN in rescue; distances
// output tolerance is 1e-3 REL at |d|~64 -> plenty).
// CTA 128x128, K=64 resident, 8 warps, warp tile 32x64.
// ---------------------------------------------------------------------------
#define AS_STRIDE 68
#define CS_STRIDE 132
#define GEMM_SMEM_BYTES (2 * 128 * AS_STRIDE * 4)

__global__ __launch_bounds__(256) void gemm_k(const float* __restrict__ A,
                                              const float* __restrict__ B,
                                              float* __restrict__ outD) {
    extern __shared__ float sm[];
    float* As = sm;                      // [128][68] tf32(A)
    float* Bs = sm + 128 * AS_STRIDE;    // [128][68] tf32(2*codebook)
    float* Cs = sm;                      // [128][132] aliases post-MMA

    const int tid = threadIdx.x;
    const int lane = tid & 31;
    const int wid = tid >> 5;
    const int g = lane >> 2;
    const int t = lane & 3;
    const int wm0 = (wid & 3) * 32;
    const int wn0 = (wid >> 2) * 64;
    const int bm0 = blockIdx.y * 128;
    const int bk0 = blockIdx.x * 128;

    {
        const float4* Ag = (const float4*)(A + (size_t)bm0 * DIM);
        const float4* Bg = (const float4*)(B + (size_t)bk0 * DIM);
#pragma unroll
        for (int i = 0; i < 8; i++) {
            int t4 = tid + i * 256;        // 0..2047
            int row = t4 >> 4;
            int c4 = (t4 & 15) * 4;
            float4 va = Ag[t4];
            float4 vh;
            vh.x = cvt_tf32(va.x);
            vh.y = cvt_tf32(va.y);
            vh.z = cvt_tf32(va.z);
            vh.w = cvt_tf32(va.w);
            *(float4*)&As[row * AS_STRIDE + c4] = vh;
            float4 vb = Bg[t4];
            float4 bh;
            bh.x = cvt_tf32(2.f * vb.x);
            bh.y = cvt_tf32(2.f * vb.y);
            bh.z = cvt_tf32(2.f * vb.z);
            bh.w = cvt_tf32(2.f * vb.w);
            *(float4*)&Bs[row * AS_STRIDE + c4] = bh;
        }
    }
    __syncthreads();

    float acc[2][8][4];
#pragma unroll
    for (int mi = 0; mi < 2; mi++)
#pragma unroll
        for (int ni = 0; ni < 8; ni++)
#pragma unroll
            for (int j = 0; j < 4; j++) acc[mi][ni][j] = 0.f;

#pragma unroll
    for (int k0 = 0; k0 < 64; k0 += 8) {
        float ah[2][4];
#pragma unroll
        for (int mi = 0; mi < 2; mi++) {
            int r0 = wm0 + mi * 16 + g;
            ah[mi][0] = As[r0 * AS_STRIDE + k0 + t];
            ah[mi][1] = As[(r0 + 8) * AS_STRIDE + k0 + t];
            ah[mi][2] = As[r0 * AS_STRIDE + k0 + t + 4];
            ah[mi][3] = As[(r0 + 8) * AS_STRIDE + k0 + t + 4];
        }
#pragma unroll
        for (int nh = 0; nh < 2; nh++) {
            float bh[4][2];
#pragma unroll
            for (int ni = 0; ni < 4; ni++) {
                int n = wn0 + (nh * 4 + ni) * 8 + g;
                bh[ni][0] = Bs[n * AS_STRIDE + k0 + t];
                bh[ni][1] = Bs[n * AS_STRIDE + k0 + t + 4];
            }
#pragma unroll
            for (int mi = 0; mi < 2; mi++)
#pragma unroll
                for (int ni = 0; ni < 4; ni++)
                    mma8(acc[mi][nh * 4 + ni], ah[mi], bh[ni]);
        }
    }

    __syncthreads();
#pragma unroll
    for (int mi = 0; mi < 2; mi++)
#pragma unroll
        for (int ni = 0; ni < 8; ni++) {
            int r0 = wm0 + mi * 16 + g;
            int c0 = wn0 + ni * 8 + 2 * t;
            Cs[r0 * CS_STRIDE + c0]           = acc[mi][ni][0];
            Cs[r0 * CS_STRIDE + c0 + 1]       = acc[mi][ni][1];
            Cs[(r0 + 8) * CS_STRIDE + c0]     = acc[mi][ni][2];
            Cs[(r0 + 8) * CS_STRIDE + c0 + 1] = acc[mi][ni][3];
        }
    __syncthreads();

    // Coalesced distance stores + candidate collection. Warp owns 16 rows.
    float cn4[4];
#pragma unroll
    for (int j = 0; j < 4; j++) cn4[j] = g_colnorm[bk0 + lane + 32 * j];

#pragma unroll 2
    for (int r = 0; r < 16; r++) {
        int lr = wid * 16 + r;
        int gr = bm0 + lr;
        float rn = g_rownorm[gr];
        const float* crow = &Cs[lr * CS_STRIDE];
        float* drow = outD + (size_t)gr * KCB + bk0;
        float v[4];
        float mn = 3.4e38f;
#pragma unroll
        for (int j = 0; j < 4; j++) {
            int c = lane + 32 * j;
            float d = (rn - crow[c]) + cn4[j];
            v[j] = d;
            drow[c] = d;
            if (d < mn) mn = d;
        }
#pragma unroll
        for (int off = 16; off > 0; off >>= 1) {
            float o = __shfl_xor_sync(0xFFFFFFFFu, mn, off);
            if (o < mn) mn = o;
        }
        float thr = mn + CAND_MARGIN;
#pragma unroll
        for (int j = 0; j < 4; j++) {
            if (v[j] <= thr) {
                int slot = atomicAdd(&g_candn[gr], 1);
                if (slot < CAND_CAP)
                    g_cand[gr][slot] = (unsigned short)(bk0 + lane + 32 * j);
            }
        }
    }
}

// ---------------------------------------------------------------------------
// rescue + outputs: block = 32 rows, 8 threads/row (thread = candidate slot).
// X rows staged in smem; exact fp32 dots with 4-way ILP; 8-lane shfl reduce.
// Writes indices, histogram, the single one-hot 1.0 (zeros pre-memset),
// and the quantized row. High occupancy, short chains.
// ---------------------------------------------------------------------------
#define RROWS 32   // rows per block
__global__ __launch_bounds__(256) void rescue_k(const float* __restrict__ X,
                                                const float* __restrict__ CB,
                                                float* __restrict__ outI,
                                                float* __restrict__ outE,
                                                float* __restrict__ outQ) {
    __shared__ float Xs[RROWS * DIM];           // 8 KB
    const int tid = threadIdx.x;
    const int r = tid >> 3;        // 0..31 row within block
    const int s = tid & 7;         // candidate slot
    const int row0 = blockIdx.x * RROWS;
    const int gr = row0 + r;

    // cooperative X stage: 32 rows x 64 floats = 512 float4
    {
        const float4* Xg = (const float4*)(X + (size_t)row0 * DIM);
        float4* Xs4 = (float4*)Xs;
#pragma unroll
        for (int i = 0; i < 2; i++) Xs4[tid + i * 256] = Xg[tid + i * 256];
    }
    __syncthreads();

    const float rn = g_rownorm[gr];
    const float* xrow = Xs + r * DIM;
    const int n = g_candn[gr];

    unsigned long long best = 0xFFFFFFFFFFFFFFFFULL;
    if (n <= CAND_CAP) {
#pragma unroll
        for (int base = 0; base < CAND_CAP; base += 8) {
            if (s + base < n) {
                int c = g_cand[gr][s + base];
                const float4* cp4 = (const float4*)(CB + (size_t)c * DIM);
                const float4* xp4 = (const float4*)xrow;
                float d0 = 0.f, d1 = 0.f, d2 = 0.f, d3 = 0.f;
#pragma unroll
                for (int i = 0; i < DIM / 4; i++) {
                    float4 x = xp4[i];
                    float4 e = cp4[i];
                    d0 = fmaf(x.x, e.x, d0);
                    d1 = fmaf(x.y, e.y, d1);
                    d2 = fmaf(x.z, e.z, d2);
                    d3 = fmaf(x.w, e.w, d3);
                }
                float dot = (d0 + d1) + (d2 + d3);
                float d = (rn - 2.f * dot) + g_colnorm[c];
                unsigned long long key =
                    ((unsigned long long)forder(d) << 32) | (unsigned)c;
                if (key < best) best = key;
            }
        }
    } else {
        // overflow fallback: exact fp32 scan of all 512 codes (8-way split)
        for (int c = s; c < KCB; c += 8) {
            const float4* cp4 = (const float4*)(CB + (size_t)c * DIM);
            const float4* xp4 = (const float4*)xrow;
            float d0 = 0.f, d1 = 0.f, d2 = 0.f, d3 = 0.f;
#pragma unroll
            for (int i = 0; i < DIM / 4; i++) {
                float4 x = xp4[i];
                float4 e = cp4[i];
                d0 = fmaf(x.x, e.x, d0);
                d1 = fmaf(x.y, e.y, d1);
                d2 = fmaf(x.z, e.z, d2);
                d3 = fmaf(x.w, e.w, d3);
            }
            float dot = (d0 + d1) + (d2 + d3);
            float d = (rn - 2.f * dot) + g_colnorm[c];
            unsigned long long key =
                ((unsigned long long)forder(d) << 32) | (unsigned)c;
            if (key < best) best = key;
        }
    }
    // reduce within the 8-lane group
#pragma unroll
    for (int off = 4; off > 0; off >>= 1) {
        unsigned long long o = __shfl_xor_sync(0xFFFFFFFFu, best, off);
        if (o < best) best = o;
    }
    int idx = (int)(best & 0xFFFFFFFFu);

    if (s == 0) {
        outI[gr] = (float)idx;
        atomicAdd(&g_count[idx], 1u);
        outE[(size_t)gr * KCB + idx] = 1.f;  // zeros pre-filled by memset
    }

    // quantized: 8 threads x 8 floats (2 float4 each); outQ 16B-aligned
    {
        const float4* cp4 = (const float4*)(CB + (size_t)idx * DIM);
        const float4* xp4 = (const float4*)xrow;
        float4* qp4 = (float4*)(outQ + (size_t)gr * DIM);
#pragma unroll
        for (int i = 0; i < 2; i++) {
            int j = s * 2 + i;
            float4 x = xp4[j];
            float4 e = cp4[j];
            float4 q;
            q.x = x.x + (e.x - x.x);
            q.y = x.y + (e.y - x.y);
            q.z = x.z + (e.z - x.z);
            q.w = x.w + (e.w - x.w);
            qp4[j] = q;
        }
    }
}

// ---------------------------------------------------------------------------
__global__ void perp_k(float* __restrict__ outP) {
    __shared__ float s[KCB];
    int t = threadIdx.x;
    float p = (float)g_count[t] / (float)N_ROWS;
    s[t] = p * logf(p + 1e-10f);
    __syncthreads();
    for (int o = KCB / 2; o > 0; o >>= 1) {
        if (t < o) s[t] += s[t + o];
        __syncthreads();
    }
    if (t == 0) outP[0] = expf(-s[0]);
}

// ---------------------------------------------------------------------------
extern "C" void kernel_launch(void* const* d_in, const int* in_sizes, int n_in,
                              void* d_out, int out_size) {
    const float* X = (const float*)d_in[0];
    const float* CB = (const float*)d_in[1];
    if (n_in >= 2 && in_sizes[0] == KCB * DIM) {
        X = (const float*)d_in[1];
        CB = (const float*)d_in[0];
    }
    float* out = (float*)d_out;
    float* outQ = out + OFF_Q;
    float* outP = out + OFF_P;
    float* outE = out + OFF_E;
    float* outI = out + OFF_I;
    float* outD = out + OFF_D;

    cudaFuncSetAttribute(gemm_k, cudaFuncAttributeMaxDynamicSharedMemorySize,
                         GEMM_SMEM_BYTES);

    // zero the one-hot encodings region (graph-capturable memset node)
    cudaMemsetAsync(outE, 0, (size_t)N_ROWS * KCB * sizeof(float));

    rownorm_k<<<N_ROWS / 256, 256>>>(X);
    colnorm_k<<<2, 256>>>(CB);
    gemm_k<<<dim3(KCB / 128, N_ROWS / 128), 256, GEMM_SMEM_BYTES>>>(X, CB, outD);
    rescue_k<<<N_ROWS / RROWS, 256>>>(X, CB, outI, outE, outQ);
    perp_k<<<1, KCB>>>(outP);
}